// round 1
// baseline (speedup 1.0000x reference)
#include <cuda_runtime.h>

#define Hd 128
#define Wd 128
#define HWd (128*128)

// Scratch (device globals: allocation-free rule)
__device__ float g_t2[4 * 64 * HWd];   // conv1 output, masked+relu  (16 MB)
__device__ float g_t3[4 * 64 * HWd];   // conv2 output, relu         (16 MB)

// ---------------------------------------------------------------------------
// K1: conv1 (1x1 grouped, 256->64 per group) + relu, active blocks only.
// grid = 512: bid -> {sub(32 oc half), g, 16x16 block}; 256 threads = 1 px each.
// ---------------------------------------------------------------------------
extern "C" __global__ void __launch_bounds__(256)
k1_conv1(const float* __restrict__ x, const float* __restrict__ mask,
         const float* __restrict__ w1)
{
    int bid = blockIdx.x;
    int sub = bid & 1;
    int gb  = bid >> 1;
    int g   = gb >> 6;
    int blk = gb & 63;
    if (mask[g * 64 + blk] <= 0.5f) return;
    int bi = blk >> 3, bj = blk & 7;

    extern __shared__ float w1s[];   // [256 ic][32 oc]
    int tid = threadIdx.x;
    for (int e = tid; e < 256 * 32; e += 256) {
        int oc_l = e & 31;
        int ic   = e >> 5;
        w1s[e] = w1[(size_t)(g * 64 + sub * 32 + oc_l) * 256 + ic];
    }
    __syncthreads();

    int p  = tid;
    int gy = bi * 16 + (p >> 4);
    int gx = bj * 16 + (p & 15);
    const float* xp = x + (size_t)(g * 256) * HWd + gy * Wd + gx;

    float acc[32];
#pragma unroll
    for (int i = 0; i < 32; ++i) acc[i] = 0.f;

    for (int ic = 0; ic < 256; ic += 4) {
        float xv0 = xp[(size_t)(ic + 0) * HWd];
        float xv1 = xp[(size_t)(ic + 1) * HWd];
        float xv2 = xp[(size_t)(ic + 2) * HWd];
        float xv3 = xp[(size_t)(ic + 3) * HWd];
        const float4* r0 = (const float4*)(w1s + (ic + 0) * 32);
        const float4* r1 = (const float4*)(w1s + (ic + 1) * 32);
        const float4* r2 = (const float4*)(w1s + (ic + 2) * 32);
        const float4* r3 = (const float4*)(w1s + (ic + 3) * 32);
#pragma unroll
        for (int j = 0; j < 8; ++j) {
            float4 a = r0[j], b = r1[j], c = r2[j], d = r3[j];
            acc[4*j+0] = fmaf(a.x, xv0, acc[4*j+0]);
            acc[4*j+1] = fmaf(a.y, xv0, acc[4*j+1]);
            acc[4*j+2] = fmaf(a.z, xv0, acc[4*j+2]);
            acc[4*j+3] = fmaf(a.w, xv0, acc[4*j+3]);
            acc[4*j+0] = fmaf(b.x, xv1, acc[4*j+0]);
            acc[4*j+1] = fmaf(b.y, xv1, acc[4*j+1]);
            acc[4*j+2] = fmaf(b.z, xv1, acc[4*j+2]);
            acc[4*j+3] = fmaf(b.w, xv1, acc[4*j+3]);
            acc[4*j+0] = fmaf(c.x, xv2, acc[4*j+0]);
            acc[4*j+1] = fmaf(c.y, xv2, acc[4*j+1]);
            acc[4*j+2] = fmaf(c.z, xv2, acc[4*j+2]);
            acc[4*j+3] = fmaf(c.w, xv2, acc[4*j+3]);
            acc[4*j+0] = fmaf(d.x, xv3, acc[4*j+0]);
            acc[4*j+1] = fmaf(d.y, xv3, acc[4*j+1]);
            acc[4*j+2] = fmaf(d.z, xv3, acc[4*j+2]);
            acc[4*j+3] = fmaf(d.w, xv3, acc[4*j+3]);
        }
    }

    float* t2p = g_t2 + (size_t)(g * 64 + sub * 32) * HWd + gy * Wd + gx;
#pragma unroll
    for (int o = 0; o < 32; ++o)
        t2p[(size_t)o * HWd] = fmaxf(acc[o], 0.f);
}

// ---------------------------------------------------------------------------
// K2: conv2 (3x3 grouped, 64->64) + relu, active blocks only.
// Halo from t2 (neighbor-inactive or out-of-image -> 0).
// grid = 512: {sub(32 oc half), g, block}; 256 threads.
// Thread tile: 4 oc x 8 px. smem: t2 halo [64][324] + w2 chunk [32ic][9][36pad].
// ---------------------------------------------------------------------------
extern "C" __global__ void __launch_bounds__(256)
k2_conv2(const float* __restrict__ mask, const float* __restrict__ w2)
{
    int bid = blockIdx.x;
    int sub = bid & 1;
    int gb  = bid >> 1;
    int g   = gb >> 6;
    int blk = gb & 63;
    const float* mg = mask + g * 64;
    if (mg[blk] <= 0.5f) return;
    int bi = blk >> 3, bj = blk & 7;

    extern __shared__ float sm[];
    float* t2s = sm;                 // 64 * 324
    float* w2s = sm + 64 * 324;      // 32 * 9 * 36

    __shared__ float nbact[9];       // 3x3 neighbor-block activity
    int tid = threadIdx.x;
    if (tid < 9) {
        int dy = tid / 3, dx = tid % 3;
        int by = bi - 1 + dy, bx = bj - 1 + dx;
        float a = 0.f;
        if ((unsigned)by < 8u && (unsigned)bx < 8u)
            a = (mg[by * 8 + bx] > 0.5f) ? 1.f : 0.f;
        nbact[tid] = a;
    }
    __syncthreads();

    // halo load: rows/cols [blk*16-1 .. blk*16+16]
    const float* t2g = g_t2 + (size_t)(g * 64) * HWd;
    for (int ic = 0; ic < 64; ++ic) {
        for (int hp = tid; hp < 324; hp += 256) {
            int hy = hp / 18, hx = hp - hy * 18;
            int ndy = (hy + 15) >> 4;     // 0 | 1 | 2
            int ndx = (hx + 15) >> 4;
            float v = 0.f;
            if (nbact[ndy * 3 + ndx] > 0.f) {
                int gy = bi * 16 - 1 + hy;
                int gx = bj * 16 - 1 + hx;
                v = t2g[(size_t)ic * HWd + gy * Wd + gx];
            }
            t2s[ic * 324 + hp] = v;
        }
    }

    int lane = tid & 31, wq = tid >> 5;
    int oc0 = wq * 4;                       // local oc within this sub's 32
    int hb[8];
#pragma unroll
    for (int k = 0; k < 8; ++k) {
        int p = lane + 32 * k;
        hb[k] = (p >> 4) * 18 + (p & 15);
    }

    float acc[4][8];
#pragma unroll
    for (int o = 0; o < 4; ++o)
#pragma unroll
        for (int k = 0; k < 8; ++k) acc[o][k] = 0.f;

    const size_t wbase = (size_t)(g * 64 + sub * 32) * 576;

    for (int ch = 0; ch < 2; ++ch) {
        int ic0 = ch * 32;
        if (ch) __syncthreads();            // protect w2s reuse
        // load w2 chunk: [icl*9+tap][oc_l] with pad 36 (coalesced global reads)
        for (int e = tid; e < 32 * 9 * 32; e += 256) {
            int oc_l = e / 288;
            int rt   = e - oc_l * 288;
            w2s[rt * 36 + oc_l] = w2[wbase + (size_t)oc_l * 576 + ic0 * 9 + rt];
        }
        __syncthreads();

        for (int icl = 0; icl < 32; ++icl) {
            const float* trow = t2s + (ic0 + icl) * 324;
#pragma unroll
            for (int t = 0; t < 9; ++t) {
                int dy = t / 3, dx = t % 3;
                float4 wv = *(const float4*)(w2s + (icl * 9 + t) * 36 + oc0);
                float tv[8];
#pragma unroll
                for (int k = 0; k < 8; ++k)
                    tv[k] = trow[hb[k] + dy * 18 + dx];
#pragma unroll
                for (int k = 0; k < 8; ++k) {
                    acc[0][k] = fmaf(wv.x, tv[k], acc[0][k]);
                    acc[1][k] = fmaf(wv.y, tv[k], acc[1][k]);
                    acc[2][k] = fmaf(wv.z, tv[k], acc[2][k]);
                    acc[3][k] = fmaf(wv.w, tv[k], acc[3][k]);
                }
            }
        }
    }

    float* t3p = g_t3 + (size_t)(g * 64 + sub * 32 + oc0) * HWd
               + (bi * 16) * Wd + bj * 16;
#pragma unroll
    for (int o = 0; o < 4; ++o)
#pragma unroll
        for (int k = 0; k < 8; ++k) {
            int p = lane + 32 * k;
            t3p[(size_t)o * HWd + (p >> 4) * Wd + (p & 15)] = fmaxf(acc[o][k], 0.f);
        }
}

// ---------------------------------------------------------------------------
// K3: conv3 (1x1 grouped, 64->256 per group) + residual + relu, all blocks.
// grid = 512: {sub(128 oc half), g, block}; 256 threads.
// Active: thread tile 8 oc x 8 px, two 64-oc chunks. Inactive: relu-copy of x.
// ---------------------------------------------------------------------------
extern "C" __global__ void __launch_bounds__(256)
k3_conv3(const float* __restrict__ x, const float* __restrict__ mask,
         const float* __restrict__ w3, float* __restrict__ out)
{
    int bid = blockIdx.x;
    int sub = bid & 1;
    int gb  = bid >> 1;
    int g   = gb >> 6;
    int blk = gb & 63;
    int bi  = blk >> 3, bj = blk & 7;
    int tid = threadIdx.x;

    int p  = tid;
    int py = p >> 4, px = p & 15;
    int gy = bi * 16 + py, gx = bj * 16 + px;

    if (mask[g * 64 + blk] <= 0.5f) {
        const float* xp = x   + (size_t)(g * 256 + sub * 128) * HWd + gy * Wd + gx;
        float*       op = out + (size_t)(g * 256 + sub * 128) * HWd + gy * Wd + gx;
#pragma unroll 4
        for (int oc = 0; oc < 128; ++oc)
            op[(size_t)oc * HWd] = fmaxf(xp[(size_t)oc * HWd], 0.f);
        return;
    }

    extern __shared__ float sm[];
    float* t3s = sm;             // 64 * 256
    float* w3s = sm + 64 * 256;  // 64 ic * 128 oc

    {
        const float* t3g = g_t3 + (size_t)(g * 64) * HWd + (bi * 16) * Wd + bj * 16;
        for (int ic = 0; ic < 64; ++ic)
            t3s[ic * 256 + p] = t3g[(size_t)ic * HWd + py * Wd + px];
    }
    for (int e = tid; e < 64 * 128; e += 256) {
        int oc_l = e & 127, ic = e >> 7;
        w3s[e] = w3[(size_t)(g * 256 + sub * 128 + oc_l) * 64 + ic];
    }
    __syncthreads();

    int lane = tid & 31, wq = tid >> 5;

    for (int ch = 0; ch < 2; ++ch) {
        int oc0 = ch * 64 + wq * 8;          // local oc within this sub's 128
        float acc[8][8];
#pragma unroll
        for (int o = 0; o < 8; ++o)
#pragma unroll
            for (int k = 0; k < 8; ++k) acc[o][k] = 0.f;

        for (int ic = 0; ic < 64; ++ic) {
            float4 wa = *(const float4*)(w3s + ic * 128 + oc0);
            float4 wb = *(const float4*)(w3s + ic * 128 + oc0 + 4);
            float tv[8];
#pragma unroll
            for (int k = 0; k < 8; ++k)
                tv[k] = t3s[ic * 256 + lane + 32 * k];
#pragma unroll
            for (int k = 0; k < 8; ++k) {
                acc[0][k] = fmaf(wa.x, tv[k], acc[0][k]);
                acc[1][k] = fmaf(wa.y, tv[k], acc[1][k]);
                acc[2][k] = fmaf(wa.z, tv[k], acc[2][k]);
                acc[3][k] = fmaf(wa.w, tv[k], acc[3][k]);
                acc[4][k] = fmaf(wb.x, tv[k], acc[4][k]);
                acc[5][k] = fmaf(wb.y, tv[k], acc[5][k]);
                acc[6][k] = fmaf(wb.z, tv[k], acc[6][k]);
                acc[7][k] = fmaf(wb.w, tv[k], acc[7][k]);
            }
        }

        const float* xp = x   + (size_t)(g * 256 + sub * 128 + oc0) * HWd
                        + (bi * 16) * Wd + bj * 16;
        float*       op = out + (size_t)(g * 256 + sub * 128 + oc0) * HWd
                        + (bi * 16) * Wd + bj * 16;
#pragma unroll
        for (int o = 0; o < 8; ++o)
#pragma unroll
            for (int k = 0; k < 8; ++k) {
                int pp = lane + 32 * k;
                size_t off = (size_t)o * HWd + (pp >> 4) * Wd + (pp & 15);
                op[off] = fmaxf(xp[off] + acc[o][k], 0.f);
            }
    }
}

// ---------------------------------------------------------------------------
extern "C" void kernel_launch(void* const* d_in, const int* in_sizes, int n_in,
                              void* d_out, int out_size)
{
    (void)in_sizes; (void)n_in; (void)out_size;
    const float* x    = (const float*)d_in[0];
    const float* mask = (const float*)d_in[1];
    const float* w1   = (const float*)d_in[2];
    const float* w2   = (const float*)d_in[3];
    const float* w3   = (const float*)d_in[4];
    float* out = (float*)d_out;

    // Idempotent, non-stream-ordered: safe under graph capture.
    cudaFuncSetAttribute(k2_conv2, cudaFuncAttributeMaxDynamicSharedMemorySize,
                         (64 * 324 + 32 * 9 * 36) * 4);
    cudaFuncSetAttribute(k3_conv3, cudaFuncAttributeMaxDynamicSharedMemorySize,
                         (64 * 256 + 64 * 128) * 4);

    k1_conv1<<<512, 256, 256 * 32 * 4>>>(x, mask, w1);
    k2_conv2<<<512, 256, (64 * 324 + 32 * 9 * 36) * 4>>>(mask, w2);
    k3_conv3<<<512, 256, (64 * 256 + 64 * 128) * 4>>>(x, mask, w3, out);
}

// round 4
// speedup vs baseline: 1.4466x; 1.4466x over previous
#include <cuda_runtime.h>

#define Hd 128
#define Wd 128
#define HWd (128*128)

// Scratch (device globals: allocation-free rule)
__device__ float g_t2[4 * 64 * HWd];   // conv1 output (active blocks only)
__device__ float g_t3[4 * 64 * HWd];   // conv2 output (active blocks only)
__device__ int   g_nact;
__device__ int   g_act[256];

// ---------------------------------------------------------------------------
// K0: compact active (g,blk) list. 1 block, 256 threads.
// ---------------------------------------------------------------------------
extern "C" __global__ void k0_compact(const float* __restrict__ mask)
{
    __shared__ int cnt;
    int t = threadIdx.x;
    if (t == 0) cnt = 0;
    __syncthreads();
    if (mask[t] > 0.5f) { int p = atomicAdd(&cnt, 1); g_act[p] = t; }
    __syncthreads();
    if (t == 0) g_nact = cnt;
}

// ---------------------------------------------------------------------------
// K1: conv1 (1x1 grouped, 256->64 per group) + relu, active blocks only.
// grid 512: (aidx, sub of 32 oc). 256 threads.
// Thread: 8 oc x 4 px (32 acc). x staged via smem, weights in smem.
// Per ic per thread: 2 LDS.128 (w) + 4 LDS (x) + 32 FFMA.
// ---------------------------------------------------------------------------
extern "C" __global__ void __launch_bounds__(256)
k1_conv1(const float* __restrict__ x, const float* __restrict__ w1)
{
    int aidx = blockIdx.x >> 1, sub = blockIdx.x & 1;
    if (aidx >= g_nact) return;
    int act = g_act[aidx];
    int g = act >> 6, blk = act & 63;
    int bi = blk >> 3, bj = blk & 7;

    extern __shared__ float sm[];
    float* ws = sm;             // [256 ic][36] (32 oc + pad)
    float* xs = sm + 256 * 36;  // [16 ic][256 px]
    int tid = threadIdx.x;

    for (int e = tid; e < 32 * 256; e += 256) {
        int oc = e >> 8, ic = e & 255;
        ws[ic * 36 + oc] = w1[(size_t)(g * 64 + sub * 32 + oc) * 256 + ic];
    }

    int ocg = tid >> 6, pxs = tid & 63;
    int oc0 = ocg * 8;
    int ty = tid >> 4, tx = tid & 15;
    const float* xb = x + (size_t)(g * 256) * HWd + (bi * 16 + ty) * Wd + bj * 16 + tx;

    float acc[8][4];
#pragma unroll
    for (int o = 0; o < 8; ++o)
#pragma unroll
        for (int k = 0; k < 4; ++k) acc[o][k] = 0.f;

    for (int c = 0; c < 16; ++c) {
#pragma unroll 4
        for (int r = 0; r < 16; ++r)
            xs[r * 256 + tid] = xb[(size_t)(c * 16 + r) * HWd];
        __syncthreads();
#pragma unroll 2
        for (int r = 0; r < 16; ++r) {
            const float* xr = xs + r * 256 + pxs;
            float t0 = xr[0], t1 = xr[64], t2 = xr[128], t3 = xr[192];
            const float4* wp = (const float4*)(ws + (c * 16 + r) * 36 + oc0);
            float4 wa = wp[0], wb = wp[1];
            float wv[8] = {wa.x, wa.y, wa.z, wa.w, wb.x, wb.y, wb.z, wb.w};
#pragma unroll
            for (int o = 0; o < 8; ++o) {
                acc[o][0] = fmaf(wv[o], t0, acc[o][0]);
                acc[o][1] = fmaf(wv[o], t1, acc[o][1]);
                acc[o][2] = fmaf(wv[o], t2, acc[o][2]);
                acc[o][3] = fmaf(wv[o], t3, acc[o][3]);
            }
        }
        __syncthreads();
    }

    float* t2p = g_t2 + (size_t)(g * 64 + sub * 32 + oc0) * HWd + (bi * 16) * Wd + bj * 16;
#pragma unroll
    for (int o = 0; o < 8; ++o)
#pragma unroll
        for (int k = 0; k < 4; ++k) {
            int px = pxs + 64 * k;
            t2p[(size_t)o * HWd + (px >> 4) * Wd + (px & 15)] = fmaxf(acc[o][k], 0.f);
        }
}

// ---------------------------------------------------------------------------
// K2: conv2 (3x3 grouped, 64->64) + relu, active blocks only.
// grid 1024: (aidx, ocsub(32oc), rowhalf(8 rows)). 256 threads.
// Halo 10x18 x64ch in smem; weights chunked 16 ic.
// Warp = (ow: 8 oc, pw: 64 px). Thread: 8 oc x 2 px (16 acc).
// ---------------------------------------------------------------------------
extern "C" __global__ void __launch_bounds__(256)
k2_conv2(const float* __restrict__ mask, const float* __restrict__ w2)
{
    int aidx = blockIdx.x >> 2, sub = (blockIdx.x >> 1) & 1, rh = blockIdx.x & 1;
    if (aidx >= g_nact) return;
    int act = g_act[aidx];
    int g = act >> 6, blk = act & 63, bi = blk >> 3, bj = blk & 7;

    extern __shared__ float sm[];
    float* t2s = sm;             // [64 ch][10*18]
    float* w2s = sm + 64 * 180;  // [16ic*9tap][36]
    __shared__ float nbact[9];

    int tid = threadIdx.x;
    const float* mg = mask + g * 64;
    if (tid < 9) {
        int dy = tid / 3, dx = tid % 3;
        int by = bi - 1 + dy, bx = bj - 1 + dx;
        nbact[tid] = ((unsigned)by < 8u && (unsigned)bx < 8u && mg[by * 8 + bx] > 0.5f) ? 1.f : 0.f;
    }
    __syncthreads();

    const float* t2g = g_t2 + (size_t)(g * 64) * HWd;
    int row0 = bi * 16 + rh * 8 - 1;
    int col0 = bj * 16 - 1;
    for (int e = tid; e < 64 * 180; e += 256) {
        int ch = e / 180, hp = e - ch * 180;
        int hy = hp / 18, hx = hp - hy * 18;
        int ndy = (rh * 8 - 1 + hy + 16) >> 4;
        int ndx = (hx + 15) >> 4;
        float v = 0.f;
        if (nbact[ndy * 3 + ndx] > 0.f)
            v = t2g[(size_t)ch * HWd + (row0 + hy) * Wd + col0 + hx];
        t2s[ch * 180 + hp] = v;
    }

    int w = tid >> 5, lane = tid & 31;
    int ow = w >> 1, pw = w & 1;
    int oc0 = ow * 8;
    int cx = lane & 15;
    int py0 = pw * 4 + (lane >> 4);      // +2k for k in {0,1}

    float acc[8][2];
#pragma unroll
    for (int o = 0; o < 8; ++o) { acc[o][0] = 0.f; acc[o][1] = 0.f; }

    const size_t wbase = (size_t)(g * 64 + sub * 32) * 576;

    for (int chk = 0; chk < 4; ++chk) {
        __syncthreads();                 // also orders halo fill before 1st compute
        int ic0 = chk * 16;
        for (int e = tid; e < 32 * 144; e += 256) {
            int oc = e / 144, rt = e - oc * 144;
            w2s[rt * 36 + oc] = w2[wbase + (size_t)oc * 576 + ic0 * 9 + rt];
        }
        __syncthreads();

        for (int icl = 0; icl < 16; ++icl) {
            const float* trow = t2s + (ic0 + icl) * 180;
#pragma unroll
            for (int dy = 0; dy < 3; ++dy) {
                float tt[3][2];
#pragma unroll
                for (int k = 0; k < 2; ++k) {
                    int base = (py0 + 2 * k + dy) * 18 + cx;
                    tt[0][k] = trow[base];
                    tt[1][k] = trow[base + 1];
                    tt[2][k] = trow[base + 2];
                }
#pragma unroll
                for (int dx = 0; dx < 3; ++dx) {
                    const float4* wp = (const float4*)(w2s + (icl * 9 + dy * 3 + dx) * 36 + oc0);
                    float4 wa = wp[0], wb = wp[1];
                    float wv[8] = {wa.x, wa.y, wa.z, wa.w, wb.x, wb.y, wb.z, wb.w};
#pragma unroll
                    for (int o = 0; o < 8; ++o) {
                        acc[o][0] = fmaf(wv[o], tt[dx][0], acc[o][0]);
                        acc[o][1] = fmaf(wv[o], tt[dx][1], acc[o][1]);
                    }
                }
            }
        }
    }

    float* t3p = g_t3 + (size_t)(g * 64 + sub * 32 + oc0) * HWd
               + (bi * 16 + rh * 8) * Wd + bj * 16;
#pragma unroll
    for (int o = 0; o < 8; ++o)
#pragma unroll
        for (int k = 0; k < 2; ++k) {
            int py = py0 + 2 * k;
            t3p[(size_t)o * HWd + py * Wd + cx] = fmaxf(acc[o][k], 0.f);
        }
}

// ---------------------------------------------------------------------------
// K3: conv3 (1x1 grouped, 64->256 per group) + residual + relu, all blocks.
// grid 512: (sub of 128 oc, g, blk). 256 threads.
// Inactive: coalesced float4 relu-copy (channel stride 4 per m!).
// Active: 4 passes x (8 oc x 4 px = 32 acc).
// ---------------------------------------------------------------------------
extern "C" __global__ void __launch_bounds__(256)
k3_conv3(const float* __restrict__ x, const float* __restrict__ mask,
         const float* __restrict__ w3, float* __restrict__ out)
{
    int sub = blockIdx.x & 1, gb = blockIdx.x >> 1;
    int g = gb >> 6, blk = gb & 63;
    int bi = blk >> 3, bj = blk & 7;
    int tid = threadIdx.x;

    if (mask[g * 64 + blk] <= 0.5f) {
        int q = tid >> 6, s = tid & 63;          // q: channel phase 0..3
        int py = s >> 2, c4 = s & 3;
        size_t base = (size_t)(g * 256 + sub * 128 + q) * HWd + (bi * 16 + py) * Wd + bj * 16;
        const float4* xp = (const float4*)(x + base) + c4;
        float4*       op = (float4*)(out + base) + c4;
#pragma unroll 4
        for (int m = 0; m < 32; ++m) {           // channels q, q+4, ..., q+124
            float4 v = xp[(size_t)(4 * m) * (HWd / 4)];
            v.x = fmaxf(v.x, 0.f); v.y = fmaxf(v.y, 0.f);
            v.z = fmaxf(v.z, 0.f); v.w = fmaxf(v.w, 0.f);
            op[(size_t)(4 * m) * (HWd / 4)] = v;
        }
        return;
    }

    extern __shared__ float sm[];
    float* t3s = sm;             // [64 ic][256 px]
    float* w3s = sm + 64 * 256;  // [64 ic][132] (128 oc + pad)

    const float* t3g = g_t3 + (size_t)(g * 64) * HWd + (bi * 16) * Wd + bj * 16;
    int ty = tid >> 4, tx = tid & 15;
#pragma unroll 4
    for (int ic = 0; ic < 64; ++ic)
        t3s[ic * 256 + tid] = t3g[(size_t)ic * HWd + ty * Wd + tx];
    for (int e = tid; e < 64 * 128; e += 256) {
        int oc = e >> 6, ic = e & 63;
        w3s[ic * 132 + oc] = w3[(size_t)(g * 256 + sub * 128 + oc) * 64 + ic];
    }
    __syncthreads();

    int w = tid >> 5, lane = tid & 31;
    int og = w >> 1, pxh = w & 1;

    for (int pass = 0; pass < 4; ++pass) {
        int ocb = pass * 32 + og * 8;
        float acc[8][4];
#pragma unroll
        for (int o = 0; o < 8; ++o)
#pragma unroll
            for (int k = 0; k < 4; ++k) acc[o][k] = 0.f;

        for (int ic = 0; ic < 64; ++ic) {
            const float4* wp = (const float4*)(w3s + ic * 132 + ocb);
            float4 wa = wp[0], wb = wp[1];
            float wv[8] = {wa.x, wa.y, wa.z, wa.w, wb.x, wb.y, wb.z, wb.w};
            const float* tr = t3s + ic * 256 + pxh * 128 + lane;
            float tv0 = tr[0], tv1 = tr[32], tv2 = tr[64], tv3 = tr[96];
#pragma unroll
            for (int o = 0; o < 8; ++o) {
                acc[o][0] = fmaf(wv[o], tv0, acc[o][0]);
                acc[o][1] = fmaf(wv[o], tv1, acc[o][1]);
                acc[o][2] = fmaf(wv[o], tv2, acc[o][2]);
                acc[o][3] = fmaf(wv[o], tv3, acc[o][3]);
            }
        }

        size_t base = (size_t)(g * 256 + sub * 128 + ocb) * HWd + (bi * 16) * Wd + bj * 16;
        const float* xp = x + base;
        float*       op = out + base;
#pragma unroll
        for (int o = 0; o < 8; ++o)
#pragma unroll
            for (int k = 0; k < 4; ++k) {
                int px = pxh * 128 + lane + 32 * k;
                size_t off = (size_t)o * HWd + (px >> 4) * Wd + (px & 15);
                op[off] = fmaxf(xp[off] + acc[o][k], 0.f);
            }
    }
}

// ---------------------------------------------------------------------------
extern "C" void kernel_launch(void* const* d_in, const int* in_sizes, int n_in,
                              void* d_out, int out_size)
{
    (void)in_sizes; (void)n_in; (void)out_size;
    const float* x    = (const float*)d_in[0];
    const float* mask = (const float*)d_in[1];
    const float* w1   = (const float*)d_in[2];
    const float* w2   = (const float*)d_in[3];
    const float* w3   = (const float*)d_in[4];
    float* out = (float*)d_out;

    const int smem1 = (256 * 36 + 16 * 256) * 4;       // 53248
    const int smem2 = (64 * 180 + 144 * 36) * 4;       // 66816
    const int smem3 = (64 * 256 + 64 * 132) * 4;       // 99328
    cudaFuncSetAttribute(k1_conv1, cudaFuncAttributeMaxDynamicSharedMemorySize, smem1);
    cudaFuncSetAttribute(k2_conv2, cudaFuncAttributeMaxDynamicSharedMemorySize, smem2);
    cudaFuncSetAttribute(k3_conv3, cudaFuncAttributeMaxDynamicSharedMemorySize, smem3);

    k0_compact<<<1, 256>>>(mask);
    k1_conv1<<<512, 256, smem1>>>(x, w1);
    k2_conv2<<<1024, 256, smem2>>>(mask, w2);
    k3_conv3<<<512, 256, smem3>>>(x, mask, w3, out);
}